// round 8
// baseline (speedup 1.0000x reference)
#include <cuda_runtime.h>
#include <cuda_bf16.h>
#include <float.h>
#include <math.h>

#define K_TOPICS 100
#define VOCAB    8192
#define TOPN     20
#define NT       256
#define CPT      4                    // CTAs per topic
#define NCTA     (K_TOPICS * CPT)     // 400
#define NW       (NT / 32)            // 8 warps

// ---- persistent device scratch (zero-initialized at module load) ----
__device__ int   g_topidx[K_TOPICS * TOPN];
__device__ float g_mn[NCTA];
__device__ float g_mx[NCTA];
__device__ int   g_arrive;     // monotone ticket (grid barrier)
__device__ int   g_done;       // monotone ticket (finalize)
__device__ float g_pos;
__device__ float g_neg;

__device__ __forceinline__ int ld_acquire(const int* p) {
    int v;
    asm volatile("ld.global.acquire.gpu.b32 %0, [%1];" : "=r"(v) : "l"(p) : "memory");
    return v;
}
__device__ __forceinline__ float ldcg_f(const float* p) {
    float v;
    asm volatile("ld.global.cg.f32 %0, [%1];" : "=f"(v) : "l"(p) : "memory");
    return v;
}
__device__ __forceinline__ int ldcg_i(const int* p) {
    int v;
    asm volatile("ld.global.cg.b32 %0, [%1];" : "=r"(v) : "l"(p) : "memory");
    return v;
}
// order-preserving float->u32 key: larger float => larger key
__device__ __forceinline__ unsigned fkey(float f) {
    unsigned b = __float_as_uint(f);
    return (b & 0x80000000u) ? ~b : (b | 0x80000000u);
}

// ----------------------------------------------------------------------------
// grid = 400 (4 CTAs per topic), block = 256, >=4 CTAs/SM residency (64 regs).
// CTA (t = bid/4, q4 = bid&3) owns columns [q4*2048, q4*2048+2048).
// ----------------------------------------------------------------------------
__global__ void __launch_bounds__(NT, 4)
fused_kernel(const float* __restrict__ beta, const float* __restrict__ W,
             const int* __restrict__ epoch_ptr, float* __restrict__ out) {
    const int bid  = blockIdx.x;
    const int t    = bid >> 2;
    const int q4   = bid & 3;
    const int tid  = threadIdx.x;
    const int lane = tid & 31;
    const int wid  = tid >> 5;

    __shared__ unsigned s_hist[256];
    __shared__ unsigned s_selbyte;
    __shared__ unsigned s_above;
    __shared__ int      s_cnt;
    __shared__ float    s_cv[128];
    __shared__ int      s_ci[128];
    __shared__ float    s_topv[TOPN];
    __shared__ int      s_topi[TOPN];
    __shared__ float    s_p[TOPN];
    __shared__ float    s_r0[NW];
    __shared__ float    s_r1[NW];
    __shared__ float    s_f0, s_f1;
    __shared__ unsigned s_bm[VOCAB / 32];   // 1 KB

    const float4* __restrict__ beta4 = (const float4*)(beta + (size_t)t * VOCAB);

    // =========== pass 0: 256-bin histogram of key[31:24] + row max ===========
    s_hist[tid] = 0u;
    __syncthreads();
    float lmax = -FLT_MAX;
    #pragma unroll
    for (int q = 0; q < 8; ++q) {
        float4 f = __ldg(&beta4[tid + NT * q]);
        const float vv[4] = { f.x, f.y, f.z, f.w };
        #pragma unroll
        for (int k = 0; k < 4; ++k) {
            lmax = fmaxf(lmax, vv[k]);
            unsigned bin = fkey(vv[k]) >> 24;
            unsigned peers = __match_any_sync(~0u, bin);   // warp-aggregate
            if ((__ffs(peers) - 1) == lane)
                atomicAdd(&s_hist[bin], (unsigned)__popc(peers));
        }
    }
    for (int o = 16; o > 0; o >>= 1) lmax = fmaxf(lmax, __shfl_xor_sync(~0u, lmax, o));
    if (lane == 0) s_r0[wid] = lmax;
    __syncthreads();                     // hist + partial maxes complete

    if (tid < 32) {                      // rank-aware bin selection, want = 20
        unsigned c[8], s = 0;
        #pragma unroll
        for (int i = 0; i < 8; ++i) { c[i] = s_hist[lane * 8 + i]; s += c[i]; }
        unsigned run = s;
        #pragma unroll
        for (int o = 1; o < 32; o <<= 1) {
            unsigned v = __shfl_down_sync(~0u, run, o);
            if (lane + o < 32) run += v;
        }
        unsigned cum = run - s;
        #pragma unroll
        for (int i = 7; i >= 0; --i) {
            if (cum < TOPN && cum + c[i] >= TOPN) {
                s_selbyte = (unsigned)(lane * 8 + i);
                s_above   = cum;
            }
            cum += c[i];
        }
    }
    if (tid == 32) {
        float m = -FLT_MAX;
        #pragma unroll
        for (int w = 0; w < NW; ++w) m = fmaxf(m, s_r0[w]);
        s_f0 = m;
    }
    __syncthreads();
    const unsigned B0     = s_selbyte;
    const unsigned want1  = TOPN - s_above;
    const float    rowmax = s_f0;

    // ===== pass 1: sub-histogram of key[23:16] within B0  +  softmax denom ====
    s_hist[tid] = 0u;
    __syncthreads();
    float z = 0.0f;
    #pragma unroll
    for (int q = 0; q < 8; ++q) {
        float4 f = __ldg(&beta4[tid + NT * q]);
        const float vv[4] = { f.x, f.y, f.z, f.w };
        #pragma unroll
        for (int k = 0; k < 4; ++k) {
            z += expf(vv[k] - rowmax);
            unsigned key = fkey(vv[k]);
            bool ok = (key >> 24) == B0;
            unsigned binx = ok ? ((key >> 16) & 0xFFu) : 0x100u;   // sentinel group
            unsigned peers = __match_any_sync(~0u, binx);
            if (ok && (__ffs(peers) - 1) == lane)
                atomicAdd(&s_hist[binx], (unsigned)__popc(peers));
        }
    }
    for (int o = 16; o > 0; o >>= 1) z += __shfl_xor_sync(~0u, z, o);
    if (lane == 0) s_r1[wid] = z;
    __syncthreads();

    if (tid < 32) {                      // rank-aware selection, want = want1
        const unsigned w = want1;
        unsigned c[8], s = 0;
        #pragma unroll
        for (int i = 0; i < 8; ++i) { c[i] = s_hist[lane * 8 + i]; s += c[i]; }
        unsigned run = s;
        #pragma unroll
        for (int o = 1; o < 32; o <<= 1) {
            unsigned v = __shfl_down_sync(~0u, run, o);
            if (lane + o < 32) run += v;
        }
        unsigned cum = run - s;
        #pragma unroll
        for (int i = 7; i >= 0; --i) {
            if (cum < w && cum + c[i] >= w) s_selbyte = (unsigned)(lane * 8 + i);
            cum += c[i];
        }
    }
    if (tid == 32) {
        float v = 0.0f;
        #pragma unroll
        for (int w = 0; w < NW; ++w) v += s_r1[w];
        s_f1 = v;
    }
    if (tid == 64) s_cnt = 0;
    __syncthreads();
    const unsigned pref16 = (B0 << 8) | s_selbyte;
    const float    invden = 1.0f / s_f1;

    // ---- compaction: keys with 16-bit prefix >= threshold (~20-25 cands) ----
    #pragma unroll
    for (int q = 0; q < 8; ++q) {
        float4 f = __ldg(&beta4[tid + NT * q]);
        const float vv[4] = { f.x, f.y, f.z, f.w };
        #pragma unroll
        for (int k = 0; k < 4; ++k) {
            if ((fkey(vv[k]) >> 16) >= pref16) {
                int p = atomicAdd(&s_cnt, 1);
                if (p < 128) { s_cv[p] = vv[k]; s_ci[p] = 4 * (tid + NT * q) + k; }
            }
        }
    }
    __syncthreads();

    // ---- warp 0: exact top-20 among candidates ----
    if (tid < 32) {
        const int C = min(s_cnt, 128);
        float cv[4]; int ci[4];
        #pragma unroll
        for (int s = 0; s < 4; ++s) {
            int p = lane + 32 * s;
            cv[s] = (p < C) ? s_cv[p] : -FLT_MAX;
            ci[s] = (p < C) ? s_ci[p] : (VOCAB - 1);
        }
        float bv = -FLT_MAX; int bi = VOCAB - 1;
        #pragma unroll
        for (int s = 0; s < 4; ++s) if (cv[s] > bv) { bv = cv[s]; bi = ci[s]; }
        for (int it = 0; it < TOPN; ++it) {
            float v = bv; int i = bi;
            #pragma unroll
            for (int o = 16; o > 0; o >>= 1) {
                float ov = __shfl_xor_sync(~0u, v, o);
                int   oi = __shfl_xor_sync(~0u, i, o);
                if (ov > v || (ov == v && oi < i)) { v = ov; i = oi; }
            }
            if (lane == 0) { s_topv[it] = v; s_topi[it] = i; }
            if (bi == i) {
                #pragma unroll
                for (int s = 0; s < 4; ++s) if (ci[s] == i) cv[s] = -FLT_MAX;
                bv = -FLT_MAX; bi = VOCAB - 1;
                #pragma unroll
                for (int s = 0; s < 4; ++s) if (cv[s] > bv) { bv = cv[s]; bi = ci[s]; }
            }
            __syncwarp();
        }
        if (lane == 0) {
            float zz = 0.0f;
            for (int j = 0; j < TOPN; ++j) zz += expf(s_topv[j] - rowmax);
            float pinv = 1.0f / zz;
            for (int j = 0; j < TOPN; ++j) s_p[j] = expf(s_topv[j] - rowmax) * pinv;
        }
    }
    __syncthreads();

    // publish own top-20 (one CTA per topic writes)
    if (q4 == 0 && tid < TOPN) g_topidx[t * TOPN + tid] = s_topi[tid];

    // this CTA's loss columns (from L1-hot beta row)
    const float4 bl = __ldg(&beta4[q4 * 512 + tid]);
    const float4 bh = __ldg(&beta4[q4 * 512 + tid + NT]);

    // =========== gather: M = p @ W over this CTA's quarter-row ===========
    const float4* __restrict__ W4 = (const float4*)W;
    const int qbase = q4 * 512;          // float4 offset of this quarter
    float4 acc0 = make_float4(0.f, 0.f, 0.f, 0.f);
    float4 acc1 = make_float4(0.f, 0.f, 0.f, 0.f);
    #pragma unroll 5
    for (int j = 0; j < TOPN; ++j) {
        const int    rowi = s_topi[j] & (VOCAB - 1);   // defense: never OOB
        const size_t base = (size_t)rowi * (VOCAB / 4) + qbase;
        const float  w    = s_p[j];
        float4 a = __ldg(&W4[base + tid]);
        float4 b = __ldg(&W4[base + tid + NT]);
        acc0.x += w * a.x; acc0.y += w * a.y; acc0.z += w * a.z; acc0.w += w * a.w;
        acc1.x += w * b.x; acc1.y += w * b.y; acc1.z += w * b.z; acc1.w += w * b.w;
    }

    // ---- partial min/max of M over this quarter ----
    float mn = fminf(fminf(fminf(acc0.x, acc0.y), fminf(acc0.z, acc0.w)),
                     fminf(fminf(acc1.x, acc1.y), fminf(acc1.z, acc1.w)));
    float mx = fmaxf(fmaxf(fmaxf(acc0.x, acc0.y), fmaxf(acc0.z, acc0.w)),
                     fmaxf(fmaxf(acc1.x, acc1.y), fmaxf(acc1.z, acc1.w)));
    for (int o = 16; o > 0; o >>= 1) {
        mn = fminf(mn, __shfl_xor_sync(~0u, mn, o));
        mx = fmaxf(mx, __shfl_xor_sync(~0u, mx, o));
    }
    if (lane == 0) { s_r0[wid] = mn; s_r1[wid] = mx; }
    __syncthreads();
    if (tid == 0) {
        float a = FLT_MAX, b = -FLT_MAX;
        #pragma unroll
        for (int w = 0; w < NW; ++w) { a = fminf(a, s_r0[w]); b = fmaxf(b, s_r1[w]); }
        g_mn[bid] = a;
        g_mx[bid] = b;
        __threadfence();
        int ticket = atomicAdd(&g_arrive, 1);
        int target = ((ticket / NCTA) + 1) * NCTA;
        // BOUNDED spin: ~4M * 32ns ~= 130ms worst case. Never hit when all
        // 400 CTAs are co-resident; converts any residency deadlock into a
        // wrong-answer signal instead of a container timeout.
        int guard = 0;
        while (ld_acquire(&g_arrive) < target && guard < (1 << 22)) {
            __nanosleep(32);
            ++guard;
        }
    }
    s_bm[tid] = 0u;                      // NT == VOCAB/32
    __syncthreads();                     // holds everyone until barrier passes

    // ---- combined min/max + "other topic" bitmap ----
    if (tid == 0) {
        float a = FLT_MAX, b = -FLT_MAX;
        #pragma unroll
        for (int c = 0; c < CPT; ++c) {
            a = fminf(a, ldcg_f(&g_mn[t * CPT + c]));
            b = fmaxf(b, ldcg_f(&g_mx[t * CPT + c]));
        }
        s_f0 = a; s_f1 = b;
    }
    for (int e = tid; e < K_TOPICS * TOPN; e += NT) {
        if ((e / TOPN) != t) {
            int idx = ldcg_i(&g_topidx[e]) & (VOCAB - 1);
            atomicOr(&s_bm[idx >> 5], 1u << (idx & 31));
        }
    }
    __syncthreads();
    const float mmin = s_f0;
    const float minv = 1.0f / (s_f1 - mmin);

    // ---- per-column loss over this CTA's 8 columns/thread ----
    float pos = 0.0f, neg = 0.0f;
    {
        const float bb[8] = { bl.x, bl.y, bl.z, bl.w, bh.x, bh.y, bh.z, bh.w };
        const float MM[8] = { acc0.x, acc0.y, acc0.z, acc0.w, acc1.x, acc1.y, acc1.z, acc1.w };
        #pragma unroll
        for (int k = 0; k < 8; ++k) {
            int f4i = (k < 4) ? (q4 * 512 + tid) : (q4 * 512 + tid + NT);
            int col = 4 * f4i + (k & 3);
            float sft = expf(bb[k] - rowmax) * invden;
            float wc  = 1.0f - (MM[k] - mmin) * minv;
            float l   = 100.0f * sft * sft * wc;
            bool  md  = (s_bm[col >> 5] >> (col & 31)) & 1u;
            if (md) pos += l; else neg += l;
        }
    }
    for (int o = 16; o > 0; o >>= 1) {
        pos += __shfl_xor_sync(~0u, pos, o);
        neg += __shfl_xor_sync(~0u, neg, o);
    }
    if (lane == 0) { s_r0[wid] = pos; s_r1[wid] = neg; }
    __syncthreads();
    if (tid == 0) {
        float P = 0.0f, N = 0.0f;
        #pragma unroll
        for (int w = 0; w < NW; ++w) { P += s_r0[w]; N += s_r1[w]; }
        atomicAdd(&g_pos, P);
        atomicAdd(&g_neg, N);
        __threadfence();
        int t2 = atomicAdd(&g_done, 1);
        if ((t2 % NCTA) == NCTA - 1) {       // last CTA of this replay
            float gp = atomicAdd(&g_pos, 0.0f);
            float gn = atomicAdd(&g_neg, 0.0f);
            const int   epoch    = epoch_ptr[0];
            const float lambda_a = (epoch < 100) ? (float)epoch : 100.0f;
            out[0] = lambda_a * (gp * 0.7f + gn * 0.3f) * 2.0f;
            g_pos = 0.0f;
            g_neg = 0.0f;
            __threadfence();
        }
    }
}

// ----------------------------------------------------------------------------
extern "C" void kernel_launch(void* const* d_in, const int* in_sizes, int n_in,
                              void* d_out, int out_size) {
    const float* beta  = nullptr;
    const float* W     = nullptr;
    const int*   epoch = nullptr;
    for (int i = 0; i < n_in; ++i) {
        if (in_sizes[i] == K_TOPICS * VOCAB)   beta  = (const float*)d_in[i];
        else if (in_sizes[i] == VOCAB * VOCAB) W     = (const float*)d_in[i];
        else if (in_sizes[i] == 1)             epoch = (const int*)d_in[i];
    }
    fused_kernel<<<NCTA, NT>>>(beta, W, epoch, (float*)d_out);
}